// round 8
// baseline (speedup 1.0000x reference)
#include <cuda_runtime.h>
#include <math.h>
#include <stdint.h>

typedef unsigned long long ull;

#define BATCH 64
#define SEQ   2048
#define IN_F  256
#define HID   512
#define RANKS 8     // CTAs per cluster; each owns 64 columns of W_hh
#define BPC   4     // batch rows per cluster

#define REG_B 1024                 // region: 64 entries x 16B
#define BUF_B (RANKS * REG_B)      // 8192 per buffer

// ---------------------------------------------------------------------------
// Packed f32x2 helpers
// ---------------------------------------------------------------------------
__device__ __forceinline__ ull ffma2(ull a, ull b, ull c) {
    ull d;
    asm("fma.rn.f32x2 %0, %1, %2, %3;" : "=l"(d) : "l"(a), "l"(b), "l"(c));
    return d;
}
__device__ __forceinline__ ull addx2(ull a, ull b) {
    ull d;
    asm("add.rn.f32x2 %0, %1, %2;" : "=l"(d) : "l"(a), "l"(b));
    return d;
}
__device__ __forceinline__ ull dup2(float x) {
    ull d;
    asm("mov.b64 %0, {%1, %1};" : "=l"(d) : "f"(x));
    return d;
}
__device__ __forceinline__ ull pack2(float lo, float hi) {
    ull d;
    asm("mov.b64 %0, {%1, %2};" : "=l"(d) : "f"(lo), "f"(hi));
    return d;
}
__device__ __forceinline__ float f2lo(ull v) {
    return __int_as_float((int)(unsigned int)(v & 0xffffffffULL));
}
__device__ __forceinline__ float f2hi(ull v) {
    return __int_as_float((int)(unsigned int)(v >> 32));
}

// ---------------------------------------------------------------------------
// mbarrier / cluster primitives
// ---------------------------------------------------------------------------
__device__ __forceinline__ void mbar_init(uint32_t mbar, uint32_t cnt) {
    asm volatile("mbarrier.init.shared.b64 [%0], %1;" :: "r"(mbar), "r"(cnt) : "memory");
}
// cluster-scope acquire wait (we consume peer-written smem after this)
__device__ __forceinline__ void mbar_wait_cl(uint32_t mbar, uint32_t parity) {
    asm volatile(
        "{\n\t"
        ".reg .pred P;\n\t"
        "WL_%=:\n\t"
        "mbarrier.try_wait.parity.acquire.cluster.shared::cta.b64 P, [%0], %1, 0x989680;\n\t"
        "@P bra.uni WD_%=;\n\t"
        "bra.uni WL_%=;\n\t"
        "WD_%=:\n\t"
        "}"
        :: "r"(mbar), "r"(parity) : "memory");
}
__device__ __forceinline__ void st_cluster_u64(uint32_t saddr, int r, ull v) {
    uint32_t ra;
    asm volatile("mapa.shared::cluster.u32 %0, %1, %2;" : "=r"(ra) : "r"(saddr), "r"(r));
    asm volatile("st.shared::cluster.u64 [%0], %1;" :: "r"(ra), "l"(v) : "memory");
}
// release-arrive on peer r's mbarrier (orders this thread's prior cluster stores)
__device__ __forceinline__ void mbar_arrive_remote(uint32_t local_mbar, int r) {
    uint32_t rm;
    asm volatile("mapa.shared::cluster.u32 %0, %1, %2;" : "=r"(rm) : "r"(local_mbar), "r"(r));
    asm volatile("mbarrier.arrive.release.cluster.shared::cluster.b64 _, [%0];"
                 :: "r"(rm) : "memory");
}
__device__ __forceinline__ void cluster_sync_() {
    asm volatile("barrier.cluster.arrive.aligned;" ::: "memory");
    asm volatile("barrier.cluster.wait.aligned;" ::: "memory");
}

// ---------------------------------------------------------------------------
// Kernel 1: x_proj GEMM  out[m][n] = sum_k X[m][k]*Wih[n][k] + bih[n] + bhh[n]
// ---------------------------------------------------------------------------
#define BM 128
#define BN 64
#define BK 32
#define ASP 130

__global__ __launch_bounds__(256) void xproj_kernel(
    const float* __restrict__ X, const float* __restrict__ Wih,
    const float* __restrict__ bih, const float* __restrict__ bhh,
    float* __restrict__ out)
{
    __shared__ float As[BK][ASP];
    __shared__ float Ws[BK][BN];

    const int tid = threadIdx.x;
    const int m0 = blockIdx.x * BM;
    const int n0 = blockIdx.y * BN;
    const int tx = tid & 15;
    const int ty = tid >> 4;

    ull acc[4][4];
#pragma unroll
    for (int r = 0; r < 4; r++)
#pragma unroll
        for (int c = 0; c < 4; c++) acc[r][c] = 0ULL;

    for (int k0 = 0; k0 < IN_F; k0 += BK) {
#pragma unroll
        for (int i = 0; i < 4; i++) {
            int idx = tid + i * 256;
            int m = idx >> 3;
            int k4 = idx & 7;
            float4 v = *(const float4*)(X + (size_t)(m0 + m) * IN_F + k0 + k4 * 4);
            As[k4 * 4 + 0][m] = v.x;
            As[k4 * 4 + 1][m] = v.y;
            As[k4 * 4 + 2][m] = v.z;
            As[k4 * 4 + 3][m] = v.w;
        }
#pragma unroll
        for (int i = 0; i < 2; i++) {
            int idx = tid + i * 256;
            int n = idx >> 3;
            int k4 = idx & 7;
            float4 v = *(const float4*)(Wih + (size_t)(n0 + n) * IN_F + k0 + k4 * 4);
            Ws[k4 * 4 + 0][n] = v.x;
            Ws[k4 * 4 + 1][n] = v.y;
            Ws[k4 * 4 + 2][n] = v.z;
            Ws[k4 * 4 + 3][n] = v.w;
        }
        __syncthreads();

#pragma unroll
        for (int k = 0; k < BK; k++) {
            ull ap[4];
#pragma unroll
            for (int r = 0; r < 4; r++)
                ap[r] = *(const ull*)&As[k][ty * 8 + 2 * r];
            float4 wv = *(const float4*)&Ws[k][tx * 4];
            ull wd0 = dup2(wv.x), wd1 = dup2(wv.y);
            ull wd2 = dup2(wv.z), wd3 = dup2(wv.w);
#pragma unroll
            for (int r = 0; r < 4; r++) {
                acc[r][0] = ffma2(ap[r], wd0, acc[r][0]);
                acc[r][1] = ffma2(ap[r], wd1, acc[r][1]);
                acc[r][2] = ffma2(ap[r], wd2, acc[r][2]);
                acc[r][3] = ffma2(ap[r], wd3, acc[r][3]);
            }
        }
        __syncthreads();
    }

    float bsum[4];
#pragma unroll
    for (int c = 0; c < 4; c++) {
        int n = n0 + tx * 4 + c;
        bsum[c] = bih[n] + bhh[n];
    }
#pragma unroll
    for (int r = 0; r < 4; r++) {
        size_t mlo = (size_t)(m0 + ty * 8 + 2 * r);
        float4 lo4, hi4;
        lo4.x = f2lo(acc[r][0]) + bsum[0]; lo4.y = f2lo(acc[r][1]) + bsum[1];
        lo4.z = f2lo(acc[r][2]) + bsum[2]; lo4.w = f2lo(acc[r][3]) + bsum[3];
        hi4.x = f2hi(acc[r][0]) + bsum[0]; hi4.y = f2hi(acc[r][1]) + bsum[1];
        hi4.z = f2hi(acc[r][2]) + bsum[2]; hi4.w = f2hi(acc[r][3]) + bsum[3];
        *(float4*)(out + mlo * HID + n0 + tx * 4)       = lo4;
        *(float4*)(out + (mlo + 1) * HID + n0 + tx * 4) = hi4;
    }
}

// ---------------------------------------------------------------------------
// Kernel 2: cluster scan with per-source pipelined h-exchange.
//
// 16 clusters x 8 CTAs; cluster owns 4 batch rows, CTA rank owns 64 cols.
// 512 threads: col = tid>>3, kq = tid&7 (k-lane). Thread's k-set:
// { src*64 + 8j + kq : j=0..7 } for each source region src = (rank+s)&7,
// processed in segment order s=0..7 (own region first, no wait).
// W in registers: w[s*8+j] = Whh[gcol][((rank+s)&7)*64 + 8j + kq].
//
// h smem: 2 buffers x 8 regions x 64 entries x 16B; entry c of region r =
// ((h_b0,h_b1),(h_b2,h_b3)) for k = r*64+c. Lane group reads entries 8j+kq:
// 8 consecutive 16B lines, 4-way broadcast across col-groups -> conflict-free.
//
// Exchange: per-(buffer,source) mbarriers, count=64. After __syncthreads
// (closing all reads of the current buffer), the 64 kq==0 writer threads
// store their 16B entry locally + to all 7 peers (st.shared::cluster) and
// release-arrive on each peer's mbar. Consumers wait region s only at
// segment s, so DSMEM transfer overlaps segments 0..s-1 compute.
// Producers serve peers in consumption order: dst = (rank - d) & 7.
// ---------------------------------------------------------------------------
__global__ void __cluster_dims__(RANKS, 1, 1) __launch_bounds__(512, 1)
scan_kernel(const float* __restrict__ h0, const float* __restrict__ Whh,
            float* __restrict__ out)
{
    __shared__ __align__(16) char hbuf[2 * BUF_B];
    __shared__ __align__(8) ull mbars[16];     // [buffer][source-rank]

    const int tid  = threadIdx.x;
    const int kq   = tid & 7;
    const int col  = tid >> 3;                 // 0..63
    const int rank = blockIdx.x & (RANKS - 1);
    const int cid  = blockIdx.x >> 3;
    const int b0   = cid * BPC;
    const int gcol = rank * 64 + col;

    // ---- W slice into registers, segment-ordered
    float w[64];
#pragma unroll
    for (int s = 0; s < 8; s++) {
        const int src = (rank + s) & 7;
        const float* wr = Whh + (size_t)gcol * HID + src * 64 + kq;
#pragma unroll
        for (int j = 0; j < 8; j++) w[s * 8 + j] = wr[j * 8];
    }

    const uint32_t hpb = (uint32_t)__cvta_generic_to_shared(hbuf);
    const uint32_t mbb = (uint32_t)__cvta_generic_to_shared(mbars);

    if (tid < 16) mbar_init(mbb + tid * 8, 64);

    // ---- preload h0 into buffer 0 (each CTA loads full h for its 4 rows)
    {
        const int k = tid;
        float v0 = h0[(size_t)(b0 + 0) * HID + k];
        float v1 = h0[(size_t)(b0 + 1) * HID + k];
        float v2 = h0[(size_t)(b0 + 2) * HID + k];
        float v3 = h0[(size_t)(b0 + 3) * HID + k];
        char* e = hbuf + (k >> 6) * REG_B + (k & 63) * 16;
        *(ull*)e       = pack2(v0, v1);
        *(ull*)(e + 8) = pack2(v2, v3);
    }
    __syncthreads();
    cluster_sync_();            // mbar inits + buffer0 visible cluster-wide

    // output lane mapping: lanes {0,1,4,5} of each 8-group own batches 0..3
    const bool outl = (kq & 2) == 0;
    const int  ob   = ((kq >> 2) << 1) | (kq & 1);
    const size_t obase = ((size_t)(b0 + ob) * SEQ) * HID + gcol;
    float xpv = outl ? out[obase] : 0.0f;

    for (int t = 0; t < SEQ; t++) {
        const int p = t & 1;
        const uint32_t par = (uint32_t)(((t >> 1) + (t & 1) + 1) & 1);

        ull a01 = 0, a23 = 0;
#pragma unroll
        for (int s = 0; s < 8; s++) {
            const int src = (rank + s) & 7;
            if (s > 0 && t > 0)
                mbar_wait_cl(mbb + (uint32_t)((p * 8 + src) * 8), par);
            const ulonglong2* base =
                (const ulonglong2*)(hbuf + p * BUF_B + src * REG_B);
#pragma unroll
            for (int j = 0; j < 8; j++) {
                ulonglong2 h2 = base[j * 8 + kq];
                ull wd = dup2(w[s * 8 + j]);
                a01 = ffma2(wd, h2.x, a01);
                a23 = ffma2(wd, h2.y, a23);
            }
        }

        // prefetch next xp while reduce/exchange happens
        float xpn = 0.0f;
        if (outl && t + 1 < SEQ) xpn = out[obase + (size_t)(t + 1) * HID];

        // split-value butterfly: lanes 0-3 end with a01 sum, 4-7 with a23 sum
        ull y = __shfl_xor_sync(0xffffffffu, (kq < 4) ? a23 : a01, 4);
        ull x = addx2((kq < 4) ? a01 : a23, y);
        x = addx2(x, __shfl_xor_sync(0xffffffffu, x, 2));
        x = addx2(x, __shfl_xor_sync(0xffffffffu, x, 1));

        float v = 0.0f;
        if (outl) {
            float sv = (kq & 1) ? f2hi(x) : f2lo(x);
            v = tanhf(sv + xpv);
            out[obase + (size_t)t * HID] = v;
        }
        xpv = xpn;

        // gather the 4 batch values to lane kq==0 of each group
        float v1 = __shfl_down_sync(0xffffffffu, v, 1);
        float v2 = __shfl_down_sync(0xffffffffu, v, 4);
        float v3 = __shfl_down_sync(0xffffffffu, v, 5);

        __syncthreads();   // ALL reads of buffer p complete before signaling
        if (t < SEQ - 1 && kq == 0) {
            const ull lo = pack2(v, v1);
            const ull hi = pack2(v2, v3);
            const uint32_t eoff =
                (uint32_t)((1 - p) * BUF_B + rank * REG_B + col * 16);
            // local copy of our region entry
            *(ull*)(hbuf + eoff)     = lo;
            *(ull*)(hbuf + eoff + 8) = hi;
            const uint32_t loff = hpb + eoff;
            const uint32_t lmb  = mbb + (uint32_t)(((1 - p) * 8 + rank) * 8);
#pragma unroll
            for (int d = 1; d < RANKS; d++) {
                const int dst = (rank - d) & (RANKS - 1);  // consumption order
                st_cluster_u64(loff,     dst, lo);
                st_cluster_u64(loff + 8, dst, hi);
                mbar_arrive_remote(lmb, dst);
            }
        }
        __syncthreads();   // local region entry visible to own next-step reads
    }

    cluster_sync_();
}

// ---------------------------------------------------------------------------
// Launch
// ---------------------------------------------------------------------------
extern "C" void kernel_launch(void* const* d_in, const int* in_sizes, int n_in,
                              void* d_out, int out_size) {
    const float* x_in = (const float*)d_in[0];
    const float* h0   = (const float*)d_in[1];
    const float* W_ih = (const float*)d_in[2];
    const float* W_hh = (const float*)d_in[3];
    const float* b_ih = (const float*)d_in[4];
    const float* b_hh = (const float*)d_in[5];
    float* out = (float*)d_out;

    dim3 gg((BATCH * SEQ) / BM, HID / BN);
    xproj_kernel<<<gg, 256>>>(x_in, W_ih, b_ih, b_hh, out);

    scan_kernel<<<(BATCH / BPC) * RANKS, 512>>>(h0, W_hh, out);
}

// round 9
// speedup vs baseline: 1.3132x; 1.3132x over previous
#include <cuda_runtime.h>
#include <math.h>
#include <stdint.h>

typedef unsigned long long ull;

#define BATCH 64
#define SEQ   2048
#define IN_F  256
#define HID   512
#define RANKS 8     // CTAs per cluster; each owns 64 columns of W_hh
#define BPC   4     // batch rows per cluster

#define REG_B 1024                 // region: 64 entries x 16B
#define BUF_B (RANKS * REG_B)      // 8192 per buffer

// ---------------------------------------------------------------------------
// Packed f32x2 helpers
// ---------------------------------------------------------------------------
__device__ __forceinline__ ull ffma2(ull a, ull b, ull c) {
    ull d;
    asm("fma.rn.f32x2 %0, %1, %2, %3;" : "=l"(d) : "l"(a), "l"(b), "l"(c));
    return d;
}
__device__ __forceinline__ ull addx2(ull a, ull b) {
    ull d;
    asm("add.rn.f32x2 %0, %1, %2;" : "=l"(d) : "l"(a), "l"(b));
    return d;
}
__device__ __forceinline__ ull dup2(float x) {
    ull d;
    asm("mov.b64 %0, {%1, %1};" : "=l"(d) : "f"(x));
    return d;
}
__device__ __forceinline__ ull pack2(float lo, float hi) {
    ull d;
    asm("mov.b64 %0, {%1, %2};" : "=l"(d) : "f"(lo), "f"(hi));
    return d;
}
__device__ __forceinline__ float f2lo(ull v) {
    return __int_as_float((int)(unsigned int)(v & 0xffffffffULL));
}
__device__ __forceinline__ float f2hi(ull v) {
    return __int_as_float((int)(unsigned int)(v >> 32));
}

// ---------------------------------------------------------------------------
// mbarrier / cluster primitives
// ---------------------------------------------------------------------------
__device__ __forceinline__ void mbar_init(uint32_t mbar, uint32_t cnt) {
    asm volatile("mbarrier.init.shared.b64 [%0], %1;" :: "r"(mbar), "r"(cnt) : "memory");
}
__device__ __forceinline__ void mbar_expect_tx(uint32_t mbar, uint32_t bytes) {
    asm volatile("mbarrier.arrive.expect_tx.shared.b64 _, [%0], %1;"
                 :: "r"(mbar), "r"(bytes) : "memory");
}
// acquire.cta wait, no long suspend hint (fast wakeup path)
__device__ __forceinline__ void mbar_wait(uint32_t mbar, uint32_t parity) {
    asm volatile(
        "{\n\t"
        ".reg .pred P;\n\t"
        "WL_%=:\n\t"
        "mbarrier.try_wait.parity.acquire.cta.shared::cta.b64 P, [%0], %1;\n\t"
        "@P bra.uni WD_%=;\n\t"
        "bra.uni WL_%=;\n\t"
        "WD_%=:\n\t"
        "}"
        :: "r"(mbar), "r"(parity) : "memory");
}
// bulk copy: our smem region -> same offset in cluster rank r, signal r's mbar
__device__ __forceinline__ void cluster_bulk_copy(uint32_t local_addr, uint32_t bytes,
                                                  uint32_t local_mbar, int r) {
    uint32_t rdst, rmb;
    asm volatile("mapa.shared::cluster.u32 %0, %1, %2;" : "=r"(rdst) : "r"(local_addr), "r"(r));
    asm volatile("mapa.shared::cluster.u32 %0, %1, %2;" : "=r"(rmb) : "r"(local_mbar), "r"(r));
    asm volatile(
        "cp.async.bulk.shared::cluster.shared::cta.mbarrier::complete_tx::bytes "
        "[%0], [%1], %2, [%3];"
        :: "r"(rdst), "r"(local_addr), "r"(bytes), "r"(rmb) : "memory");
}
__device__ __forceinline__ void cluster_sync_() {
    asm volatile("barrier.cluster.arrive.aligned;" ::: "memory");
    asm volatile("barrier.cluster.wait.aligned;" ::: "memory");
}

// ---------------------------------------------------------------------------
// Kernel 1: x_proj GEMM  out[m][n] = sum_k X[m][k]*Wih[n][k] + bih[n] + bhh[n]
// ---------------------------------------------------------------------------
#define BM 128
#define BN 64
#define BK 32
#define ASP 130

__global__ __launch_bounds__(256) void xproj_kernel(
    const float* __restrict__ X, const float* __restrict__ Wih,
    const float* __restrict__ bih, const float* __restrict__ bhh,
    float* __restrict__ out)
{
    __shared__ float As[BK][ASP];
    __shared__ float Ws[BK][BN];

    const int tid = threadIdx.x;
    const int m0 = blockIdx.x * BM;
    const int n0 = blockIdx.y * BN;
    const int tx = tid & 15;
    const int ty = tid >> 4;

    ull acc[4][4];
#pragma unroll
    for (int r = 0; r < 4; r++)
#pragma unroll
        for (int c = 0; c < 4; c++) acc[r][c] = 0ULL;

    for (int k0 = 0; k0 < IN_F; k0 += BK) {
#pragma unroll
        for (int i = 0; i < 4; i++) {
            int idx = tid + i * 256;
            int m = idx >> 3;
            int k4 = idx & 7;
            float4 v = *(const float4*)(X + (size_t)(m0 + m) * IN_F + k0 + k4 * 4);
            As[k4 * 4 + 0][m] = v.x;
            As[k4 * 4 + 1][m] = v.y;
            As[k4 * 4 + 2][m] = v.z;
            As[k4 * 4 + 3][m] = v.w;
        }
#pragma unroll
        for (int i = 0; i < 2; i++) {
            int idx = tid + i * 256;
            int n = idx >> 3;
            int k4 = idx & 7;
            float4 v = *(const float4*)(Wih + (size_t)(n0 + n) * IN_F + k0 + k4 * 4);
            Ws[k4 * 4 + 0][n] = v.x;
            Ws[k4 * 4 + 1][n] = v.y;
            Ws[k4 * 4 + 2][n] = v.z;
            Ws[k4 * 4 + 3][n] = v.w;
        }
        __syncthreads();

#pragma unroll
        for (int k = 0; k < BK; k++) {
            ull ap[4];
#pragma unroll
            for (int r = 0; r < 4; r++)
                ap[r] = *(const ull*)&As[k][ty * 8 + 2 * r];
            float4 wv = *(const float4*)&Ws[k][tx * 4];
            ull wd0 = dup2(wv.x), wd1 = dup2(wv.y);
            ull wd2 = dup2(wv.z), wd3 = dup2(wv.w);
#pragma unroll
            for (int r = 0; r < 4; r++) {
                acc[r][0] = ffma2(ap[r], wd0, acc[r][0]);
                acc[r][1] = ffma2(ap[r], wd1, acc[r][1]);
                acc[r][2] = ffma2(ap[r], wd2, acc[r][2]);
                acc[r][3] = ffma2(ap[r], wd3, acc[r][3]);
            }
        }
        __syncthreads();
    }

    float bsum[4];
#pragma unroll
    for (int c = 0; c < 4; c++) {
        int n = n0 + tx * 4 + c;
        bsum[c] = bih[n] + bhh[n];
    }
#pragma unroll
    for (int r = 0; r < 4; r++) {
        size_t mlo = (size_t)(m0 + ty * 8 + 2 * r);
        float4 lo4, hi4;
        lo4.x = f2lo(acc[r][0]) + bsum[0]; lo4.y = f2lo(acc[r][1]) + bsum[1];
        lo4.z = f2lo(acc[r][2]) + bsum[2]; lo4.w = f2lo(acc[r][3]) + bsum[3];
        hi4.x = f2hi(acc[r][0]) + bsum[0]; hi4.y = f2hi(acc[r][1]) + bsum[1];
        hi4.z = f2hi(acc[r][2]) + bsum[2]; hi4.w = f2hi(acc[r][3]) + bsum[3];
        *(float4*)(out + mlo * HID + n0 + tx * 4)       = lo4;
        *(float4*)(out + (mlo + 1) * HID + n0 + tx * 4) = hi4;
    }
}

// ---------------------------------------------------------------------------
// Kernel 2: cluster scan. Per-(buffer,source) mbarriers + per-peer bulk-copy
// exchange issued by 7 separate warps.
//
// 16 clusters x 8 CTAs; cluster owns 4 batch rows, CTA rank owns 64 cols.
// 512 threads: col = tid>>3, kq = tid&7. Segment s=0..7 processes source
// region src=(rank+s)&7; s=0 is our own region (locally written, no wait);
// s>=1 waits mbar M[buf][src] which the peer's single bulk copy signals via
// complete_tx (1024 bytes). Transfers overlap earlier segments' compute.
//
// W regs: w[s*8+j] = Whh[gcol][((rank+s)&7)*64 + 8j + kq].
// h smem: 2 buffers x 8 regions x 64 entries x 16B; entry c of region r =
// ((h_b0,h_b1),(h_b2,h_b3)) for k = r*64+c. Lane group reads entries 8j+kq:
// 8 consecutive 16B lines, 4-way broadcast -> conflict-free.
//
// Per step: [waits+segments on buf p] -> reduce -> tanh -> gather ->
// writers STS own region of buf 1-p -> __syncthreads -> tid0 re-arms
// M[p][*] expects; warps 1..7 (elected lane) fence + bulk-send our region to
// peer (rank-w)&7 signaling its M[1-p][rank] -> STG out, xp prefetch.
// Safety: peer completes on M[p] are gated by peer's step t+1 waits, which
// are gated by our step-t sends -> always after our expect re-arm.
// ---------------------------------------------------------------------------
__global__ void __cluster_dims__(RANKS, 1, 1) __launch_bounds__(512, 1)
scan_kernel(const float* __restrict__ h0, const float* __restrict__ Whh,
            float* __restrict__ out)
{
    __shared__ __align__(16) char hbuf[2 * BUF_B];
    __shared__ __align__(8) ull mbars[16];     // [buffer][source-rank]

    const int tid  = threadIdx.x;
    const int kq   = tid & 7;
    const int col  = tid >> 3;                 // 0..63
    const int wsid = tid >> 5;                 // warp id 0..15
    const int rank = blockIdx.x & (RANKS - 1);
    const int cid  = blockIdx.x >> 3;
    const int b0   = cid * BPC;
    const int gcol = rank * 64 + col;

    // ---- W slice into registers, segment-ordered
    float w[64];
#pragma unroll
    for (int s = 0; s < 8; s++) {
        const int src = (rank + s) & 7;
        const float* wr = Whh + (size_t)gcol * HID + src * 64 + kq;
#pragma unroll
        for (int j = 0; j < 8; j++) w[s * 8 + j] = wr[j * 8];
    }

    const uint32_t hpb = (uint32_t)__cvta_generic_to_shared(hbuf);
    const uint32_t mbb = (uint32_t)__cvta_generic_to_shared(mbars);

    if (tid < 16) mbar_init(mbb + tid * 8, 1);
    __syncthreads();
    // prologue: arm buffer-1 mbars (consumed at t=1 from peers' step-0 sends)
    if (tid == 0) {
#pragma unroll
        for (int s = 1; s < 8; s++)
            mbar_expect_tx(mbb + (uint32_t)((8 + ((rank + s) & 7)) * 8), REG_B);
    }

    // ---- preload h0 into buffer 0
    {
        const int k = tid;
        float v0 = h0[(size_t)(b0 + 0) * HID + k];
        float v1 = h0[(size_t)(b0 + 1) * HID + k];
        float v2 = h0[(size_t)(b0 + 2) * HID + k];
        float v3 = h0[(size_t)(b0 + 3) * HID + k];
        char* e = hbuf + (k >> 6) * REG_B + (k & 63) * 16;
        *(ull*)e       = pack2(v0, v1);
        *(ull*)(e + 8) = pack2(v2, v3);
    }
    __syncthreads();
    cluster_sync_();            // mbar inits + prologue expects + buf0 visible

    // output lane mapping: lanes {0,1,4,5} of each 8-group own batches 0..3
    const bool outl = (kq & 2) == 0;
    const int  ob   = ((kq >> 2) << 1) | (kq & 1);
    const size_t obase = ((size_t)(b0 + ob) * SEQ) * HID + gcol;
    float xpv = outl ? out[obase] : 0.0f;

    for (int t = 0; t < SEQ; t++) {
        const int p = t & 1;
        const uint32_t par = (uint32_t)(((t - 1) >> 1) & 1);
        const char* bufp = hbuf + p * BUF_B;

        ull a01 = 0, a23 = 0;
        // segment 0: own region, no wait
        {
            const ulonglong2* base = (const ulonglong2*)(bufp + rank * REG_B);
#pragma unroll
            for (int j = 0; j < 8; j++) {
                ulonglong2 h2 = base[j * 8 + kq];
                ull wd = dup2(w[j]);
                a01 = ffma2(wd, h2.x, a01);
                a23 = ffma2(wd, h2.y, a23);
            }
        }
#pragma unroll
        for (int s = 1; s < 8; s++) {
            const int src = (rank + s) & 7;
            if (t > 0) mbar_wait(mbb + (uint32_t)((p * 8 + src) * 8), par);
            const ulonglong2* base = (const ulonglong2*)(bufp + src * REG_B);
#pragma unroll
            for (int j = 0; j < 8; j++) {
                ulonglong2 h2 = base[j * 8 + kq];
                ull wd = dup2(w[s * 8 + j]);
                a01 = ffma2(wd, h2.x, a01);
                a23 = ffma2(wd, h2.y, a23);
            }
        }

        // prefetch next xp (latency hidden behind reduce/exchange)
        float xpn = 0.0f;
        if (outl && t + 1 < SEQ) xpn = out[obase + (size_t)(t + 1) * HID];

        // split-value butterfly: lanes 0-3 end with a01 sum, 4-7 with a23 sum
        ull y = __shfl_xor_sync(0xffffffffu, (kq < 4) ? a23 : a01, 4);
        ull x = addx2((kq < 4) ? a01 : a23, y);
        x = addx2(x, __shfl_xor_sync(0xffffffffu, x, 2));
        x = addx2(x, __shfl_xor_sync(0xffffffffu, x, 1));

        float v = 0.0f;
        if (outl) {
            float sv = (kq & 1) ? f2hi(x) : f2lo(x);
            v = tanhf(sv + xpv);
        }
        xpv = xpn;

        // gather the 4 batch values to lane kq==0 of each group
        float v1 = __shfl_down_sync(0xffffffffu, v, 1);
        float v2 = __shfl_down_sync(0xffffffffu, v, 4);
        float v3 = __shfl_down_sync(0xffffffffu, v, 5);

        // writers assemble our region of buffer 1-p locally (pre-sync)
        if (t < SEQ - 1 && kq == 0) {
            char* e = hbuf + (1 - p) * BUF_B + rank * REG_B + col * 16;
            *(ull*)e       = pack2(v, v1);
            *(ull*)(e + 8) = pack2(v2, v3);
        }

        __syncthreads();   // closes all reads of buf p + all writer STS

        if (t < SEQ - 1) {
            // re-arm current buffer's mbars for step t+2 receives
            if (tid == 0) {
#pragma unroll
                for (int s = 1; s < 8; s++)
                    mbar_expect_tx(mbb + (uint32_t)((p * 8 + ((rank + s) & 7)) * 8),
                                   REG_B);
            }
            // warps 1..7: each sends our new region to one peer, in the
            // order peers will consume it (peer (rank-w)&7 needs us at seg w)
            if (wsid >= 1 && wsid <= 7 && (tid & 31) == 0) {
                asm volatile("fence.proxy.async.shared::cta;" ::: "memory");
                const int dst = (rank - wsid) & (RANKS - 1);
                const uint32_t src_a = hpb + (uint32_t)((1 - p) * BUF_B + rank * REG_B);
                const uint32_t mb_a  = mbb + (uint32_t)(((1 - p) * 8 + rank) * 8);
                cluster_bulk_copy(src_a, REG_B, mb_a, dst);
            }
        }

        // output store off the critical path
        if (outl) out[obase + (size_t)t * HID] = v;
    }

    cluster_sync_();
}

// ---------------------------------------------------------------------------
// Launch
// ---------------------------------------------------------------------------
extern "C" void kernel_launch(void* const* d_in, const int* in_sizes, int n_in,
                              void* d_out, int out_size) {
    const float* x_in = (const float*)d_in[0];
    const float* h0   = (const float*)d_in[1];
    const float* W_ih = (const float*)d_in[2];
    const float* W_hh = (const float*)d_in[3];
    const float* b_ih = (const float*)d_in[4];
    const float* b_hh = (const float*)d_in[5];
    float* out = (float*)d_out;

    dim3 gg((BATCH * SEQ) / BM, HID / BN);
    xproj_kernel<<<gg, 256>>>(x_in, W_ih, b_ih, b_hh, out);

    scan_kernel<<<(BATCH / BPC) * RANKS, 512>>>(h0, W_hh, out);
}